// round 1
// baseline (speedup 1.0000x reference)
#include <cuda_runtime.h>

#define B_    4
#define N_    4096
#define K_    16
#define CIN   128
#define H     256
#define COUT  128
#define NODES (B_*N_)   // 16384

// Scratch (device globals: allocation-free per harness rules)
__device__ float g_A [NODES*H];   // feats @ W1[:128]   (self half)
__device__ float g_Bm[NODES*H];   // feats @ W1[128:]   (neighbor half)
__device__ float g_S [NODES*H];   // sum_k mask*h2

// ---------------------------------------------------------------------------
// Kernel 1:  [16384 x 128] @ [128 x 512]  ->  g_A | g_Bm
// Tile: BM=128, BN=128, BK=32. 256 threads, 8x8 accum per thread.
// blockIdx.y: 0,1 -> A halves; 2,3 -> B halves.
// ---------------------------------------------------------------------------
__global__ __launch_bounds__(256, 2)
void k1_gemm(const float* __restrict__ feats, const float* __restrict__ W1)
{
    __shared__ float sF[128*36];   // padded rows (36 floats) to spread banks
    __shared__ float sW[32*128];

    int tid = threadIdx.x;
    int tx = tid & 15, ty = tid >> 4;
    int m0 = blockIdx.x * 128;
    int by = blockIdx.y;
    const float* Wbase = W1 + ((by >> 1) ? (128*256) : 0) + (by & 1) * 128;
    float* Out = ((by >> 1) ? g_Bm : g_A) + (by & 1) * 128;

    float acc[8][8];
    #pragma unroll
    for (int i = 0; i < 8; ++i)
        #pragma unroll
        for (int j = 0; j < 8; ++j) acc[i][j] = 0.f;

    for (int kc = 0; kc < 4; ++kc) {
        #pragma unroll
        for (int it = 0; it < 4; ++it) {           // feats tile [128][32]
            int t4 = tid + 256*it;
            int r = t4 >> 3, c4 = t4 & 7;
            float4 v = *(const float4*)(feats + (m0 + r)*CIN + kc*32 + c4*4);
            *(float4*)(sF + r*36 + c4*4) = v;
        }
        #pragma unroll
        for (int it = 0; it < 4; ++it) {           // W tile [32][128]
            int t4 = tid + 256*it;
            int r = t4 >> 5, j4 = t4 & 31;
            float4 v = *(const float4*)(Wbase + (kc*32 + r)*256 + j4*4);
            *(float4*)(sW + r*128 + j4*4) = v;
        }
        __syncthreads();
        #pragma unroll 8
        for (int kk = 0; kk < 32; ++kk) {
            float a[8], w[8];
            #pragma unroll
            for (int i = 0; i < 8; ++i) a[i] = sF[(ty + 16*i)*36 + kk];
            #pragma unroll
            for (int j = 0; j < 8; ++j) w[j] = sW[kk*128 + tx + 16*j];
            #pragma unroll
            for (int i = 0; i < 8; ++i)
                #pragma unroll
                for (int j = 0; j < 8; ++j) acc[i][j] += a[i]*w[j];
        }
        __syncthreads();
    }

    #pragma unroll
    for (int i = 0; i < 8; ++i) {
        int m = m0 + ty + 16*i;
        #pragma unroll
        for (int j = 0; j < 8; ++j)
            Out[m*H + tx + 16*j] = acc[i][j];
    }
}

// ---------------------------------------------------------------------------
// Kernel 2: fused edge MLP layer 2 + masked K-reduction.
// CTA = 8 nodes x 16 neighbors = 128 edges.
//   h1[e] = relu(A[node] + Bm[gather] + b1)           (smem, 128x256 fp32)
//   h2[e] = relu(h1 @ W2 + b2)                        (tiled GEMM, 8x8/thread)
//   S[node] = sum_k valid * h2                        (in-smem reduce)
// 512 threads: tx = lane (outputs), ty = warp (edges e = ty + 16*i).
// ---------------------------------------------------------------------------
__global__ __launch_bounds__(512, 1)
void k2_edge(const int* __restrict__ n_idxs, const int* __restrict__ nvalid,
             const float* __restrict__ W2, const float* __restrict__ b1,
             const float* __restrict__ b2)
{
    extern __shared__ float smem[];
    float* sh1 = smem;                 // 128*256 floats (also reused for partials)
    float* sW  = smem + 128*256;       // 64*256 floats
    float* sb  = sW + 64*256;          // 512 floats (b1|b2)
    int*   s_idx = (int*)(sb + 512);   // 128
    int*   s_val = s_idx + 128;        // 128

    int tid = threadIdx.x;
    int tx = tid & 31, ty = tid >> 5;
    int node0 = blockIdx.x * 8;

    if (tid < 128) {
        s_idx[tid] = n_idxs[node0*K_ + tid];
        s_val[tid] = nvalid[node0*K_ + tid];
    }
    if (tid < 256) sb[tid] = b1[tid];
    else           sb[tid] = b2[tid - 256];
    __syncthreads();

    // Build h1 tile: 8192 float4, 16 per thread
    #pragma unroll
    for (int it = 0; it < 16; ++it) {
        int t4 = tid + 512*it;
        int e = t4 >> 6, c4 = t4 & 63;
        int g  = node0 + (e >> 4);
        int gn = (g >> 12) * N_ + s_idx[e];
        float4 a  = *(const float4*)(g_A  + g *H + c4*4);
        float4 b  = *(const float4*)(g_Bm + gn*H + c4*4);
        float4 bb = *(const float4*)(sb + c4*4);
        float4 h;
        h.x = fmaxf(a.x + b.x + bb.x, 0.f);
        h.y = fmaxf(a.y + b.y + bb.y, 0.f);
        h.z = fmaxf(a.z + b.z + bb.z, 0.f);
        h.w = fmaxf(a.w + b.w + bb.w, 0.f);
        *(float4*)(sh1 + e*H + c4*4) = h;
    }
    __syncthreads();

    float acc[8][8];
    #pragma unroll
    for (int i = 0; i < 8; ++i)
        #pragma unroll
        for (int j = 0; j < 8; ++j) acc[i][j] = 0.f;

    for (int kc = 0; kc < 4; ++kc) {
        #pragma unroll
        for (int it = 0; it < 8; ++it) {           // W2 chunk [64][256]
            int t4 = tid + 512*it;
            int r = t4 >> 6, c4 = t4 & 63;
            *(float4*)(sW + r*256 + c4*4) =
                *(const float4*)(W2 + (kc*64 + r)*256 + c4*4);
        }
        __syncthreads();
        const float* h1k = sh1 + kc*64;
        #pragma unroll 8
        for (int kk = 0; kk < 64; ++kk) {
            float a[8], w[8];
            #pragma unroll
            for (int i = 0; i < 8; ++i) a[i] = h1k[(ty + 16*i)*H + kk];  // warp broadcast
            #pragma unroll
            for (int j = 0; j < 8; ++j) w[j] = sW[kk*256 + tx + 32*j];   // conflict-free
            #pragma unroll
            for (int i = 0; i < 8; ++i)
                #pragma unroll
                for (int j = 0; j < 8; ++j) acc[i][j] += a[i]*w[j];
        }
        __syncthreads();
    }

    // bias + relu + mask -> partials in sh1 laid out [ty][node i][o]
    #pragma unroll
    for (int i = 0; i < 8; ++i) {
        float m = s_val[i*16 + ty] ? 1.f : 0.f;     // edge e = i*16 + ty
        #pragma unroll
        for (int j = 0; j < 8; ++j) {
            int o = tx + 32*j;
            sh1[ty*2048 + i*256 + o] = fmaxf(acc[i][j] + sb[256 + o], 0.f) * m;
        }
    }
    __syncthreads();

    // reduce over 16 warps (k dim) -> g_S
    #pragma unroll
    for (int r = 0; r < 4; ++r) {
        int oi = tid + 512*r;                        // i*256 + o, 0..2047
        float s = 0.f;
        #pragma unroll
        for (int w = 0; w < 16; ++w) s += sh1[w*2048 + oi];
        g_S[node0*H + oi] = s;
    }
}

// ---------------------------------------------------------------------------
// Kernel 3:  out = g_S[16384x256] @ W3[256x128] + b3 * valid_count
// ---------------------------------------------------------------------------
__global__ __launch_bounds__(256, 2)
void k3_gemm(const int* __restrict__ nvalid, const float* __restrict__ W3,
             const float* __restrict__ b3, float* __restrict__ out)
{
    __shared__ float sS[128*36];
    __shared__ float sW[32*128];
    __shared__ float sb3[128];
    __shared__ float s_cnt[128];

    int tid = threadIdx.x;
    int tx = tid & 15, ty = tid >> 4;
    int m0 = blockIdx.x * 128;

    if (tid < 128) {
        sb3[tid] = b3[tid];
        int c = 0;
        #pragma unroll
        for (int k = 0; k < K_; ++k) c += nvalid[(m0 + tid)*K_ + k];
        s_cnt[tid] = (float)c;
    }

    float acc[8][8];
    #pragma unroll
    for (int i = 0; i < 8; ++i)
        #pragma unroll
        for (int j = 0; j < 8; ++j) acc[i][j] = 0.f;

    for (int kc = 0; kc < 8; ++kc) {
        #pragma unroll
        for (int it = 0; it < 4; ++it) {           // S tile [128][32]
            int t4 = tid + 256*it;
            int r = t4 >> 3, c4 = t4 & 7;
            *(float4*)(sS + r*36 + c4*4) =
                *(const float4*)(g_S + (m0 + r)*H + kc*32 + c4*4);
        }
        #pragma unroll
        for (int it = 0; it < 4; ++it) {           // W3 tile [32][128]
            int t4 = tid + 256*it;
            int r = t4 >> 5, j4 = t4 & 31;
            *(float4*)(sW + r*128 + j4*4) =
                *(const float4*)(W3 + (kc*32 + r)*COUT + j4*4);
        }
        __syncthreads();
        #pragma unroll 8
        for (int kk = 0; kk < 32; ++kk) {
            float a[8], w[8];
            #pragma unroll
            for (int i = 0; i < 8; ++i) a[i] = sS[(ty + 16*i)*36 + kk];
            #pragma unroll
            for (int j = 0; j < 8; ++j) w[j] = sW[kk*128 + tx + 16*j];
            #pragma unroll
            for (int i = 0; i < 8; ++i)
                #pragma unroll
                for (int j = 0; j < 8; ++j) acc[i][j] += a[i]*w[j];
        }
        __syncthreads();
    }

    #pragma unroll
    for (int i = 0; i < 8; ++i) {
        int m = ty + 16*i;
        #pragma unroll
        for (int j = 0; j < 8; ++j) {
            int o = tx + 16*j;
            out[(m0 + m)*COUT + o] = acc[i][j] + sb3[o]*s_cnt[m];
        }
    }
}

// ---------------------------------------------------------------------------
extern "C" void kernel_launch(void* const* d_in, const int* in_sizes, int n_in,
                              void* d_out, int out_size)
{
    // metadata order: keys, points, feats, n_idxs, neighbor_valid,
    //                 W1, b1, W2, b2, W3, b3   (keys/points unused)
    const float* feats  = (const float*)d_in[2];
    const int*   n_idxs = (const int*)  d_in[3];
    const int*   nvalid = (const int*)  d_in[4];
    const float* W1     = (const float*)d_in[5];
    const float* b1     = (const float*)d_in[6];
    const float* W2     = (const float*)d_in[7];
    const float* b2     = (const float*)d_in[8];
    const float* W3     = (const float*)d_in[9];
    const float* b3     = (const float*)d_in[10];
    float* out = (float*)d_out;

    const int smem2 = (128*256 + 64*256 + 512)*4 + 256*4;   // 199680 B
    cudaFuncSetAttribute(k2_edge, cudaFuncAttributeMaxDynamicSharedMemorySize, smem2);

    k1_gemm<<<dim3(NODES/128, 4), 256>>>(feats, W1);
    k2_edge<<<NODES/8, 512, smem2>>>(n_idxs, nvalid, W2, b1, b2);
    k3_gemm<<<NODES/128, 256>>>(nvalid, W3, b3, out);
}